// round 11
// baseline (speedup 1.0000x reference)
#include <cuda_runtime.h>
#include <math.h>
#include <limits.h>

#define NRR   4096
#define NLL   16384
#define KM    8
#define TK    10
#define CF    16
#define NB    4
#define CDX   3
#define CDY   11
#define CDZ   11
#define NCELL (CDX*CDY*CDZ)      // 363
#define NCB   (NB*NCELL)         // 1452
#define WPB   8                  // warps per block in k_main
#define GRD   (NRR/WPB)          // 512 blocks
#define BINB  64                 // k_bin blocks (co-resident trivially)
#define CAPL  8                  // per-lane candidate slots
#define KNONE 0xFFFFFFFFu
#define FULLM 0xFFFFFFFFu
#define F_LOG2PI 1.8378770664093453f

// ---------------- device scratch (zero-initialized at load) ----------------
__device__ int       g_ccnt[NCB];        // self-resetting (scan phase zeroes it)
__device__ int       g_cstart[NCB + 1];
__device__ int       g_ccur[NCB];
__device__ long long g_cent[NLL];        // ((c1<<16|c2<<8|c3) << 16) | lidar_idx
__device__ int       g_fb[NB * TK];      // lowest indices NOT in batch b
__device__ float4    g_part[NRR];
__device__ int       g_done;             // self-resetting
__device__ int       g_bb_cnt, g_bb_gen; // k_bin barrier (cnt self-resets, gen monotone)

__device__ __forceinline__ float softplusf(float x) {
    return log1pf(expf(-fabsf(x))) + fmaxf(x, 0.0f);
}

// grid barrier for k_bin (exactly BINB co-resident blocks)
__device__ __forceinline__ void binsync() {
    __threadfence();
    __syncthreads();
    if (threadIdx.x == 0) {
        int gen = *(volatile int*)&g_bb_gen;
        if (atomicAdd(&g_bb_cnt, 1) == BINB - 1) {
            g_bb_cnt = 0;
            __threadfence();
            *(volatile int*)&g_bb_gen = gen + 1;
        } else {
            while (*(volatile int*)&g_bb_gen == gen) {}
        }
        __threadfence();
    }
    __syncthreads();
}

// ---------------- binning: count -> scan(+self-zero) -> scatter, one launch ----------------
__global__ __launch_bounds__(256) void k_bin(const int* __restrict__ lidx) {
    __shared__ int s_scan[256];
    const int tid = threadIdx.x, bid = blockIdx.x;
    const int gid = bid * 256 + tid;                    // 64*256 == NLL exactly

    const int4 v = reinterpret_cast<const int4*>(lidx)[gid];
    const int cell = v.x * NCELL + (((v.y >> 4) * CDY + (v.z >> 4)) * CDZ + (v.w >> 4));
    atomicAdd(&g_ccnt[cell], 1);

    if (bid == 1 && tid < NB) {                          // -inf tie fillers
        int c = 0;
        for (int j = 0; j < NLL && c < TK; ++j)
            if (lidx[j * 4] != tid) g_fb[tid * TK + c++] = j;
    }
    binsync();

    if (bid == 0) {                                      // exclusive scan of 1452 cells
        const int base = tid * 6;
        int c[6], s = 0;
        #pragma unroll
        for (int q = 0; q < 6; ++q) {
            const int idx = base + q;
            c[q] = (idx < NCB) ? g_ccnt[idx] : 0;
            s += c[q];
        }
        s_scan[tid] = s;
        __syncthreads();
        for (int d = 1; d < 256; d <<= 1) {
            int vv = (tid >= d) ? s_scan[tid - d] : 0;
            __syncthreads();
            s_scan[tid] += vv;
            __syncthreads();
        }
        int e = s_scan[tid] - s;
        #pragma unroll
        for (int q = 0; q < 6; ++q) {
            const int idx = base + q;
            if (idx < NCB) { g_cstart[idx] = e; g_ccur[idx] = e; g_ccnt[idx] = 0; }
            e += c[q];
        }
        if (tid == 255) g_cstart[NCB] = s_scan[255];
    }
    binsync();

    const int pos = atomicAdd(&g_ccur[cell], 1);         // scatter (v still in regs)
    g_cent[pos] = (((long long)((v.y << 16) | (v.z << 8) | v.w)) << 16) | (long long)gid;
}

// ---------------- main: one warp per radar, register-resident candidates ----------------
__global__ __launch_bounds__(256) void k_main(
    const float* __restrict__ mu_off,  const float* __restrict__ log_sig_off,
    const float* __restrict__ mu_int,  const float* __restrict__ occ_logit,
    const float* __restrict__ mix_logit, const float* __restrict__ lfeat,
    const int* __restrict__ ridx, const int* __restrict__ lidx,
    float* __restrict__ out)
{
    __shared__ float  s_cmp[WPB][KM][9];
    __shared__ double s_red[256][4];
    __shared__ int    s_last;

    const int tid = threadIdx.x, lane = tid & 31, wid = tid >> 5;
    const int i = blockIdx.x * WPB + wid;

    const int4 r = reinterpret_cast<const int4*>(ridx)[i];
    const int b = r.x, r1 = r.y, r2 = r.z, r3 = r.w;
    const int cx = r1 >> 4, cy = r2 >> 4, cz = r3 >> 4;
    const int cbase = b * NCELL;
    const int bbeg = g_cstart[cbase];
    const int bend = g_cstart[cbase + NCELL];
    const int nbL  = bend - bbeg;

    // ---- candidate collection into per-lane registers ----
    unsigned mk[CAPL];
    bool fellback = false;
    {
        int R = 1; unsigned capv = 256u;
        while (true) {
            const int x0 = max(cx - R, 0), x1 = min(cx + R, CDX - 1);
            const int y0 = max(cy - R, 0), y1 = min(cy + R, CDY - 1);
            const int z0 = max(cz - R, 0), z1 = min(cz + R, CDZ - 1);
            int g = INT_MAX;
            if (x0 > 0)       g = min(g, r1 - x0 * 16);
            if (x1 < CDX - 1) g = min(g, (x1 + 1) * 16 - r1);
            if (y0 > 0)       g = min(g, r2 - y0 * 16);
            if (y1 < CDY - 1) g = min(g, (y1 + 1) * 16 - r2);
            if (z0 > 0)       g = min(g, r3 - z0 * 16);
            if (z1 < CDZ - 1) g = min(g, (z1 + 1) * 16 - r3);
            const bool whole = (g == INT_MAX);
            const unsigned g2 = whole ? 0x7FFFFFFFu : (unsigned)(g * g);
            const unsigned g2e = min(g2, capv);

            #pragma unroll
            for (int s = 0; s < CAPL; ++s) mk[s] = KNONE;
            bool ovf = false;

            // one contiguous span per x-slab (superset cells provably filtered by g2e)
            #pragma unroll 1
            for (int xx = x0; xx <= x1; ++xx) {
                const int beg = g_cstart[cbase + (xx * CDY + y0) * CDZ + z0];
                const int end = g_cstart[cbase + (xx * CDY + y1) * CDZ + z1 + 1];
                for (int j0 = beg; j0 < end; j0 += 32) {
                    const int j = j0 + lane;
                    if (j < end) {
                        const long long e = g_cent[j];
                        const int p  = (int)(e >> 16);
                        const int d3 = (p & 255) - r3;
                        const int d2 = ((p >> 8) & 255) - r2;
                        const int d1 = ((p >> 16) & 255) - r1;
                        const unsigned dd = (unsigned)(d1 * d1 + d2 * d2 + d3 * d3);
                        if (dd < g2e) {
                            const unsigned key = (dd << 16) | ((unsigned)e & 0xFFFFu);
                            bool ins = false;
                            #pragma unroll
                            for (int s = 0; s < CAPL; ++s)
                                if (!ins && mk[s] == KNONE) { mk[s] = key; ins = true; }
                            if (!ins) ovf = true;
                        }
                    }
                }
            }
            int myc = 0;
            #pragma unroll
            for (int s = 0; s < CAPL; ++s) myc += (mk[s] != KNONE);
            const unsigned cnt = __reduce_add_sync(FULLM, (unsigned)myc);
            const bool aovf = __any_sync(FULLM, ovf);
            if (aovf) { fellback = true; break; }
            if (cnt >= TK) break;
            if (capv < g2) { capv = g2; continue; }   // relax cap, same region
            if (whole) break;                         // exhausted: cnt == nbL < TK
            ++R; capv = 0xFFFFFFFFu;
        }
    }

    // ---- top-10 extraction (unordered set; keys reproduce (d2, idx) order exactly) ----
    unsigned mykey = KNONE;
    if (!fellback) {
        #pragma unroll
        for (int t = 0; t < TK; ++t) {
            unsigned mymin = KNONE;
            #pragma unroll
            for (int s = 0; s < CAPL; ++s) mymin = min(mymin, mk[s]);
            const unsigned best = __reduce_min_sync(FULLM, mymin);
            if (lane == t) mykey = best;
            #pragma unroll
            for (int s = 0; s < CAPL; ++s) if (mk[s] == best) mk[s] = KNONE;
        }
    } else {
        // exact whole-batch fallback (pathological data only)
        long long last = -1;
        #pragma unroll 1
        for (int t = 0; t < TK; ++t) {
            unsigned best = KNONE;
            for (int q = bbeg + lane; q < bend; q += 32) {
                const long long e = g_cent[q];
                const int p  = (int)(e >> 16);
                const int d3 = (p & 255) - r3;
                const int d2 = ((p >> 8) & 255) - r2;
                const int d1 = ((p >> 16) & 255) - r1;
                const unsigned dd = (unsigned)(d1 * d1 + d2 * d2 + d3 * d3);
                const unsigned v2 = (dd << 16) | ((unsigned)e & 0xFFFFu);
                if ((long long)v2 > last && v2 < best) best = v2;
            }
            best = __reduce_min_sync(FULLM, best);
            if (lane == t) mykey = best;
            last = (long long)best;
        }
    }

    // ---- per-component precompute (lanes 0..7, width-8 trees) ----
    {
        const int k = lane;
        float v = (k < KM) ? mix_logit[i * KM + k] : -INFINITY;
        float mx = v;
        #pragma unroll
        for (int d = 4; d; d >>= 1) mx = fmaxf(mx, __shfl_xor_sync(FULLM, mx, d));
        float ex = (k < KM) ? expf(v - mx) : 0.0f;
        float sm = ex;
        #pragma unroll
        for (int d = 4; d; d >>= 1) sm += __shfl_xor_sync(FULLM, sm, d);
        float lz = mx + logf(sm);

        float o = (k < KM) ? occ_logit[i * KM + k] : -INFINITY;
        #pragma unroll
        for (int d = 4; d; d >>= 1) o = fmaxf(o, __shfl_xor_sync(FULLM, o, d));

        if (k < KM) {
            const int bk = (i * KM + k) * 3;
            float l0 = log_sig_off[bk], l1 = log_sig_off[bk + 1], l2 = log_sig_off[bk + 2];
            s_cmp[wid][k][0] = v - lz;
            s_cmp[wid][k][1] = mu_off[bk];
            s_cmp[wid][k][2] = mu_off[bk + 1];
            s_cmp[wid][k][3] = mu_off[bk + 2];
            s_cmp[wid][k][4] = 1.0f / (expf(2.0f * l0) + 1e-12f);
            s_cmp[wid][k][5] = 1.0f / (expf(2.0f * l1) + 1e-12f);
            s_cmp[wid][k][6] = 1.0f / (expf(2.0f * l2) + 1e-12f);
            s_cmp[wid][k][7] = 2.0f * (l0 + l1 + l2) + 3.0f * F_LOG2PI;
            s_cmp[wid][k][8] = mu_int[i * KM + k];
        }
        __syncwarp();

        // ---- per-slot MDN + intensity (lanes 0..9) ----
        const bool matched = nbL > 0;
        const unsigned rm = __ballot_sync(FULLM, mykey != KNONE && lane < TK);
        const int nvalid = __popc(rm);
        float SL = 0.0f, SI = 0.0f;
        if (lane < TK) {
            const int j = (mykey != KNONE) ? (int)(mykey & 0xFFFFu)
                                           : g_fb[b * TK + (lane - nvalid)];
            const int4 lv = reinterpret_cast<const int4*>(lidx)[j];
            const float y0 = matched ? (float)(lv.w - r3) : 0.0f;
            const float y1 = matched ? (float)(lv.z - r2) : 0.0f;
            const float y2 = matched ? (float)(lv.y - r1) : 0.0f;
            const float* f = lfeat + j * CF;
            const float gi = matched ? 0.25f * (f[3] + f[7] + f[11] + f[15]) : 0.0f;

            float lp[KM]; float pm = -INFINITY;
            #pragma unroll
            for (int kk = 0; kk < KM; ++kk) {
                const float d0 = y0 - s_cmp[wid][kk][1];
                const float d1 = y1 - s_cmp[wid][kk][2];
                const float d2 = y2 - s_cmp[wid][kk][3];
                const float qv = d0 * d0 * s_cmp[wid][kk][4] + d1 * d1 * s_cmp[wid][kk][5]
                               + d2 * d2 * s_cmp[wid][kk][6];
                lp[kk] = -0.5f * (qv + s_cmp[wid][kk][7]) + s_cmp[wid][kk][0];
                pm = fmaxf(pm, lp[kk]);
            }
            float se = 0.0f;
            #pragma unroll
            for (int kk = 0; kk < KM; ++kk) se += expf(lp[kk] - pm);
            const float logp = pm + logf(se);
            SL = logp;
            float ai = 0.0f;
            #pragma unroll
            for (int kk = 0; kk < KM; ++kk)
                ai += expf(lp[kk] - logp) * fabsf(s_cmp[wid][kk][8] - gi);
            SI = ai;
        }
        #pragma unroll
        for (int d = 16; d; d >>= 1) {
            SL += __shfl_xor_sync(FULLM, SL, d);
            SI += __shfl_xor_sync(FULLM, SI, d);
        }
        if (lane == 0) {
            const float tgt = matched ? 1.0f : 0.0f;
            const float occ = tgt * softplusf(-o) + (1.0f - tgt) * softplusf(o);
            g_part[i] = make_float4(occ, tgt, tgt * SL, tgt * SI);
        }
    }

    // ---- last-block deterministic reduction; g_done self-resets ----
    __threadfence();
    __syncthreads();
    if (tid == 0) s_last = (atomicAdd(&g_done, 1) == (int)gridDim.x - 1);
    __syncthreads();
    if (s_last) {
        __threadfence();
        double a0 = 0, a1 = 0, a2 = 0, a3 = 0;
        for (int q = tid; q < NRR; q += 256) {
            const float4 p = g_part[q];
            a0 += p.x; a1 += p.y; a2 += p.z; a3 += p.w;
        }
        s_red[tid][0] = a0; s_red[tid][1] = a1; s_red[tid][2] = a2; s_red[tid][3] = a3;
        __syncthreads();
        for (int s = 128; s; s >>= 1) {
            if (tid < s) {
                s_red[tid][0] += s_red[tid + s][0];
                s_red[tid][1] += s_red[tid + s][1];
                s_red[tid][2] += s_red[tid + s][2];
                s_red[tid][3] += s_red[tid + s][3];
            }
            __syncthreads();
        }
        if (tid == 0) {
            const double occ_loss = s_red[0][0] / (double)NRR;
            const double cntm     = s_red[0][1];
            const double mdn_nll  = -s_red[0][2] / (cntm * (double)TK);
            const double int_loss =  s_red[0][3] / (cntm * (double)TK * (double)KM);
            out[0] = (float)(0.2 * occ_loss + 1.0 * mdn_nll + 0.1 * int_loss);
            g_done = 0;   // reset for next graph replay
        }
    }
}

// ---------------- launch ----------------
extern "C" void kernel_launch(void* const* d_in, const int* in_sizes, int n_in,
                              void* d_out, int out_size) {
    const float* mu_off      = (const float*)d_in[0];
    const float* log_sig_off = (const float*)d_in[1];
    const float* mu_int      = (const float*)d_in[2];
    const float* occ_logit   = (const float*)d_in[3];
    const float* mix_logit   = (const float*)d_in[4];
    const float* lfeat       = (const float*)d_in[5];
    const int*   ridx        = (const int*)d_in[6];
    const int*   lidx        = (const int*)d_in[7];
    (void)in_sizes; (void)n_in; (void)out_size;

    k_bin<<<BINB, 256>>>(lidx);
    k_main<<<GRD, 256>>>(mu_off, log_sig_off, mu_int, occ_logit, mix_logit,
                         lfeat, ridx, lidx, (float*)d_out);
}

// round 12
// speedup vs baseline: 1.4265x; 1.4265x over previous
#include <cuda_runtime.h>
#include <math.h>
#include <limits.h>

#define NRR   4096
#define NLL   16384
#define KM    8
#define TK    10
#define CF    16
#define NB    4
#define CDX   3
#define CDY   11
#define CDZ   11
#define NCELL (CDX*CDY*CDZ)      // 363
#define NCB   (NB*NCELL)         // 1452
#define WPB   8                  // warps per block
#define GRD   (NRR/WPB)          // 512 blocks, 1 radar per warp
#define CAPW  512
#define KNONE 0xFFFFFFFFu
#define FULLM 0xFFFFFFFFu
#define F_LOG2PI 1.8378770664093453f

// ---------------- device scratch (zero-initialized at load) ----------------
__device__ int       g_ccnt[NCB];        // self-resetting (scan phase zeroes it)
__device__ int       g_cstart[NCB + 1];
__device__ int       g_ccur[NCB];
__device__ long long g_cent[NLL];        // ((c1<<16|c2<<8|c3) << 16) | lidar_idx
__device__ int       g_fb[NB * TK];      // lowest indices NOT in batch b
__device__ float4    g_part[NRR];
__device__ int       g_done;             // ticket; self-resetting
__device__ int       g_bar_cnt;          // barrier count; self-resetting
__device__ int       g_bar_gen;          // barrier generation; monotone across replays

__device__ __forceinline__ float softplusf(float x) {
    return log1pf(expf(-fabsf(x))) + fmaxf(x, 0.0f);
}

// grid barrier: all GRD blocks are co-resident by construction (launch_bounds(256,4))
__device__ __forceinline__ void gsync() {
    __threadfence();
    __syncthreads();
    if (threadIdx.x == 0) {
        const int gen = *(volatile int*)&g_bar_gen;
        if (atomicAdd(&g_bar_cnt, 1) == GRD - 1) {
            g_bar_cnt = 0;
            __threadfence();
            *(volatile int*)&g_bar_gen = gen + 1;
        } else {
            while (*(volatile int*)&g_bar_gen == gen) {}
        }
        __threadfence();
    }
    __syncthreads();
}

// ---------------- single fused kernel: 512 blocks, full search parallelism ----------------
__global__ __launch_bounds__(256, 4) void k_go(
    const float* __restrict__ mu_off,  const float* __restrict__ log_sig_off,
    const float* __restrict__ mu_int,  const float* __restrict__ occ_logit,
    const float* __restrict__ mix_logit, const float* __restrict__ lfeat,
    const int* __restrict__ ridx, const int* __restrict__ lidx,
    float* __restrict__ out)
{
    __shared__ unsigned s_buf[WPB][CAPW];   // 16 KB
    __shared__ float    s_cmp[WPB][KM][9];  // 2.25 KB
    __shared__ int      s_scan[256];        // 1 KB
    __shared__ double   s_red[256][4];      // 8 KB
    __shared__ int      s_last;

    const int tid = threadIdx.x, lane = tid & 31, wid = tid >> 5;
    const int bid = blockIdx.x;

    // ---- P0: count (32 points per block, warp 0) + fb (block 1) ----
    if (tid < 32) {
        const int p = bid * 32 + tid;                      // GRD*32 == NLL exactly
        const int4 v = reinterpret_cast<const int4*>(lidx)[p];
        const int cell = v.x * NCELL + (((v.y >> 4) * CDY + (v.z >> 4)) * CDZ + (v.w >> 4));
        atomicAdd(&g_ccnt[cell], 1);
    }
    if (bid == 1 && tid < NB) {                            // -inf tie fillers
        int c = 0;
        for (int j = 0; j < NLL && c < TK; ++j)
            if (lidx[j * 4] != tid) g_fb[tid * TK + c++] = j;
    }
    gsync();

    // ---- P1: block 0 exclusive scan over 1452 cells (+ self-zero counts) ----
    if (bid == 0) {
        const int base = tid * 6;
        int c[6], s = 0;
        #pragma unroll
        for (int q = 0; q < 6; ++q) {
            const int idx = base + q;
            c[q] = (idx < NCB) ? g_ccnt[idx] : 0;
            s += c[q];
        }
        s_scan[tid] = s;
        __syncthreads();
        for (int d = 1; d < 256; d <<= 1) {
            const int vv = (tid >= d) ? s_scan[tid - d] : 0;
            __syncthreads();
            s_scan[tid] += vv;
            __syncthreads();
        }
        int e = s_scan[tid] - s;
        #pragma unroll
        for (int q = 0; q < 6; ++q) {
            const int idx = base + q;
            if (idx < NCB) { g_cstart[idx] = e; g_ccur[idx] = e; g_ccnt[idx] = 0; }
            e += c[q];
        }
        if (tid == 255) g_cstart[NCB] = s_scan[255];
    }
    gsync();

    // ---- P2: scatter (32 points per block, warp 0) ----
    if (tid < 32) {
        const int p = bid * 32 + tid;
        const int4 v = reinterpret_cast<const int4*>(lidx)[p];
        const int cell = v.x * NCELL + (((v.y >> 4) * CDY + (v.z >> 4)) * CDZ + (v.w >> 4));
        const int pos = atomicAdd(&g_ccur[cell], 1);
        g_cent[pos] = (((long long)((v.y << 16) | (v.z << 8) | v.w)) << 16) | (long long)p;
    }
    gsync();

    // ---- P3: per-radar grid-accelerated top-10 + MDN (one warp per radar) ----
    {
        const int i = bid * WPB + wid;
        const int4 r = reinterpret_cast<const int4*>(ridx)[i];
        const int b = r.x, r1 = r.y, r2 = r.z, r3 = r.w;
        const int cx = r1 >> 4, cy = r2 >> 4, cz = r3 >> 4;
        const int cbase = b * NCELL;
        const int bbeg = g_cstart[cbase];
        const int bend = g_cstart[cbase + NCELL];
        const int nbL  = bend - bbeg;

        int cnt = 0;
        #pragma unroll 1
        for (int R = 1;; ++R) {
            const int x0 = max(cx - R, 0), x1 = min(cx + R, CDX - 1);
            const int y0 = max(cy - R, 0), y1 = min(cy + R, CDY - 1);
            const int z0 = max(cz - R, 0), z1 = min(cz + R, CDZ - 1);
            int g = INT_MAX;
            if (x0 > 0)       g = min(g, r1 - x0 * 16);
            if (x1 < CDX - 1) g = min(g, (x1 + 1) * 16 - r1);
            if (y0 > 0)       g = min(g, r2 - y0 * 16);
            if (y1 < CDY - 1) g = min(g, (y1 + 1) * 16 - r2);
            if (z0 > 0)       g = min(g, r3 - z0 * 16);
            if (z1 < CDZ - 1) g = min(g, (z1 + 1) * 16 - r3);
            const bool whole = (g == INT_MAX);
            const unsigned g2 = whole ? 0x7FFFFFFFu : (unsigned)(g * g);

            cnt = 0;
            #pragma unroll 1
            for (int xx = x0; xx <= x1; ++xx) {
                #pragma unroll 1
                for (int yy = y0; yy <= y1; ++yy) {
                    const int crow = cbase + (xx * CDY + yy) * CDZ;
                    const int beg = g_cstart[crow + z0];
                    const int end = g_cstart[crow + z1 + 1];
                    for (int j0 = beg; j0 < end; j0 += 32) {
                        const int j = j0 + lane;
                        bool pred = false; unsigned key = 0;
                        if (j < end) {
                            const long long e = g_cent[j];
                            const int p  = (int)(e >> 16);
                            const int d3 = (p & 255) - r3;
                            const int d2 = ((p >> 8) & 255) - r2;
                            const int d1 = ((p >> 16) & 255) - r1;
                            const unsigned dd = (unsigned)(d1 * d1 + d2 * d2 + d3 * d3);
                            if (dd < g2) { pred = true; key = (dd << 16) | ((unsigned)e & 0xFFFFu); }
                        }
                        const unsigned m = __ballot_sync(FULLM, pred);
                        if (pred) {
                            const int off = cnt + __popc(m & ((1u << lane) - 1u));
                            if (off < CAPW) s_buf[wid][off] = key;
                        }
                        cnt += __popc(m);
                    }
                }
            }
            if (cnt >= TK || whole) break;
        }
        __syncwarp();

        // exact top-10 extraction (keys reproduce (d2, idx) order bit-exactly)
        unsigned mykey = KNONE;
        long long last = -1;
        if (cnt <= CAPW) {
            #pragma unroll
            for (int t = 0; t < TK; ++t) {
                unsigned best = KNONE;
                for (int q = lane; q < cnt; q += 32) {
                    const unsigned v = s_buf[wid][q];
                    if ((long long)v > last && v < best) best = v;
                }
                best = __reduce_min_sync(FULLM, best);
                if (lane == t) mykey = best;
                last = (long long)best;
            }
        } else {
            // overflow fallback: exact extraction over whole batch (pathological only)
            #pragma unroll 1
            for (int t = 0; t < TK; ++t) {
                unsigned best = KNONE;
                for (int q = bbeg + lane; q < bend; q += 32) {
                    const long long e = g_cent[q];
                    const int p  = (int)(e >> 16);
                    const int d3 = (p & 255) - r3;
                    const int d2 = ((p >> 8) & 255) - r2;
                    const int d1 = ((p >> 16) & 255) - r1;
                    const unsigned dd = (unsigned)(d1 * d1 + d2 * d2 + d3 * d3);
                    const unsigned v = (dd << 16) | ((unsigned)e & 0xFFFFu);
                    if ((long long)v > last && v < best) best = v;
                }
                best = __reduce_min_sync(FULLM, best);
                if (lane == t) mykey = best;
                last = (long long)best;
            }
        }

        // per-component precompute (lanes 0..7, width-8 trees)
        const int k = lane;
        float v = (k < KM) ? mix_logit[i * KM + k] : -INFINITY;
        float mx = v;
        #pragma unroll
        for (int d = 4; d; d >>= 1) mx = fmaxf(mx, __shfl_xor_sync(FULLM, mx, d));
        const float ex = (k < KM) ? expf(v - mx) : 0.0f;
        float sm = ex;
        #pragma unroll
        for (int d = 4; d; d >>= 1) sm += __shfl_xor_sync(FULLM, sm, d);
        const float lz = mx + logf(sm);

        float o = (k < KM) ? occ_logit[i * KM + k] : -INFINITY;
        #pragma unroll
        for (int d = 4; d; d >>= 1) o = fmaxf(o, __shfl_xor_sync(FULLM, o, d));

        if (k < KM) {
            const int bk = (i * KM + k) * 3;
            const float l0 = log_sig_off[bk], l1 = log_sig_off[bk + 1], l2 = log_sig_off[bk + 2];
            s_cmp[wid][k][0] = v - lz;
            s_cmp[wid][k][1] = mu_off[bk];
            s_cmp[wid][k][2] = mu_off[bk + 1];
            s_cmp[wid][k][3] = mu_off[bk + 2];
            s_cmp[wid][k][4] = 1.0f / (expf(2.0f * l0) + 1e-12f);
            s_cmp[wid][k][5] = 1.0f / (expf(2.0f * l1) + 1e-12f);
            s_cmp[wid][k][6] = 1.0f / (expf(2.0f * l2) + 1e-12f);
            s_cmp[wid][k][7] = 2.0f * (l0 + l1 + l2) + 3.0f * F_LOG2PI;
            s_cmp[wid][k][8] = mu_int[i * KM + k];
        }
        __syncwarp();

        // per-slot MDN + intensity (lanes 0..9)
        const bool matched = nbL > 0;
        const unsigned rm = __ballot_sync(FULLM, mykey != KNONE && lane < TK);
        const int nvalid = __popc(rm);
        float SL = 0.0f, SI = 0.0f;
        if (lane < TK) {
            const int j = (mykey != KNONE) ? (int)(mykey & 0xFFFFu)
                                           : g_fb[b * TK + (lane - nvalid)];
            const int4 lv = reinterpret_cast<const int4*>(lidx)[j];
            const float y0 = matched ? (float)(lv.w - r3) : 0.0f;
            const float y1 = matched ? (float)(lv.z - r2) : 0.0f;
            const float y2 = matched ? (float)(lv.y - r1) : 0.0f;
            const float* f = lfeat + j * CF;
            const float gi = matched ? 0.25f * (f[3] + f[7] + f[11] + f[15]) : 0.0f;

            float lp[KM]; float pm = -INFINITY;
            #pragma unroll
            for (int kk = 0; kk < KM; ++kk) {
                const float d0 = y0 - s_cmp[wid][kk][1];
                const float d1 = y1 - s_cmp[wid][kk][2];
                const float d2 = y2 - s_cmp[wid][kk][3];
                const float qv = d0 * d0 * s_cmp[wid][kk][4] + d1 * d1 * s_cmp[wid][kk][5]
                               + d2 * d2 * s_cmp[wid][kk][6];
                lp[kk] = -0.5f * (qv + s_cmp[wid][kk][7]) + s_cmp[wid][kk][0];
                pm = fmaxf(pm, lp[kk]);
            }
            float se = 0.0f;
            #pragma unroll
            for (int kk = 0; kk < KM; ++kk) se += expf(lp[kk] - pm);
            const float logp = pm + logf(se);
            SL = logp;
            float ai = 0.0f;
            #pragma unroll
            for (int kk = 0; kk < KM; ++kk)
                ai += expf(lp[kk] - logp) * fabsf(s_cmp[wid][kk][8] - gi);
            SI = ai;
        }
        #pragma unroll
        for (int d = 16; d; d >>= 1) {
            SL += __shfl_xor_sync(FULLM, SL, d);
            SI += __shfl_xor_sync(FULLM, SI, d);
        }
        if (lane == 0) {
            const float tgt = matched ? 1.0f : 0.0f;
            const float occ = tgt * softplusf(-o) + (1.0f - tgt) * softplusf(o);
            g_part[i] = make_float4(occ, tgt, tgt * SL, tgt * SI);
        }
    }

    // ---- P4: last-finishing-block deterministic reduction (ticket) ----
    __threadfence();
    __syncthreads();
    if (tid == 0) s_last = (atomicAdd(&g_done, 1) == GRD - 1);
    __syncthreads();
    if (s_last) {
        __threadfence();
        double a0 = 0, a1 = 0, a2 = 0, a3 = 0;
        for (int q = tid; q < NRR; q += 256) {
            const float4 p = g_part[q];
            a0 += p.x; a1 += p.y; a2 += p.z; a3 += p.w;
        }
        s_red[tid][0] = a0; s_red[tid][1] = a1; s_red[tid][2] = a2; s_red[tid][3] = a3;
        __syncthreads();
        for (int s = 128; s; s >>= 1) {
            if (tid < s) {
                s_red[tid][0] += s_red[tid + s][0];
                s_red[tid][1] += s_red[tid + s][1];
                s_red[tid][2] += s_red[tid + s][2];
                s_red[tid][3] += s_red[tid + s][3];
            }
            __syncthreads();
        }
        if (tid == 0) {
            const double occ_loss = s_red[0][0] / (double)NRR;
            const double cntm     = s_red[0][1];
            const double mdn_nll  = -s_red[0][2] / (cntm * (double)TK);
            const double int_loss =  s_red[0][3] / (cntm * (double)TK * (double)KM);
            out[0] = (float)(0.2 * occ_loss + 1.0 * mdn_nll + 0.1 * int_loss);
            g_done = 0;   // reset for next replay
        }
    }
}

// ---------------- launch ----------------
extern "C" void kernel_launch(void* const* d_in, const int* in_sizes, int n_in,
                              void* d_out, int out_size) {
    const float* mu_off      = (const float*)d_in[0];
    const float* log_sig_off = (const float*)d_in[1];
    const float* mu_int      = (const float*)d_in[2];
    const float* occ_logit   = (const float*)d_in[3];
    const float* mix_logit   = (const float*)d_in[4];
    const float* lfeat       = (const float*)d_in[5];
    const int*   ridx        = (const int*)d_in[6];
    const int*   lidx        = (const int*)d_in[7];
    (void)in_sizes; (void)n_in; (void)out_size;

    k_go<<<GRD, 256>>>(mu_off, log_sig_off, mu_int, occ_logit, mix_logit,
                       lfeat, ridx, lidx, (float*)d_out);
}

// round 13
// speedup vs baseline: 1.5521x; 1.0880x over previous
#include <cuda_runtime.h>
#include <math.h>
#include <limits.h>

#define NRR   4096
#define NLL   16384
#define KM    8
#define TK    10
#define CF    16
#define NB    4
#define CDX   3
#define CDY   11
#define CDZ   11
#define NCELL (CDX*CDY*CDZ)      // 363
#define NCB   (NB*NCELL)         // 1452
#define WPB   8                  // warps per block
#define GRD   (NRR/WPB)          // 512 blocks, 1 radar per warp
#define KNONE 0xFFFFFFFFu
#define FULLM 0xFFFFFFFFu
#define F_LOG2PI 1.8378770664093453f

// ---------------- device scratch (zero-initialized at load) ----------------
__device__ int       g_ccnt[NCB];        // self-resetting (scan phase zeroes it)
__device__ int       g_cstart[NCB + 1];
__device__ int       g_ccur[NCB];
__device__ long long g_cent[NLL];        // ((c1<<16|c2<<8|c3) << 16) | lidar_idx
__device__ int       g_fb[NB * TK];      // lowest indices NOT in batch b
__device__ float4    g_part[NRR];
__device__ int       g_done;             // ticket; self-resetting
__device__ int       g_bar_cnt;          // barrier count; self-resetting
__device__ int       g_bar_gen;          // barrier generation; monotone across replays

__device__ __forceinline__ float softplusf(float x) {
    return log1pf(expf(-fabsf(x))) + fmaxf(x, 0.0f);
}

// grid barrier: all GRD blocks are co-resident by construction (launch_bounds(256,4))
__device__ __forceinline__ void gsync() {
    __threadfence();
    __syncthreads();
    if (threadIdx.x == 0) {
        const int gen = *(volatile int*)&g_bar_gen;
        if (atomicAdd(&g_bar_cnt, 1) == GRD - 1) {
            g_bar_cnt = 0;
            __threadfence();
            *(volatile int*)&g_bar_gen = gen + 1;
        } else {
            while (*(volatile int*)&g_bar_gen == gen) {}
        }
        __threadfence();
    }
    __syncthreads();
}

// ---------------- single fused kernel ----------------
__global__ __launch_bounds__(256, 4) void k_go(
    const float* __restrict__ mu_off,  const float* __restrict__ log_sig_off,
    const float* __restrict__ mu_int,  const float* __restrict__ occ_logit,
    const float* __restrict__ mix_logit, const float* __restrict__ lfeat,
    const int* __restrict__ ridx, const int* __restrict__ lidx,
    float* __restrict__ out)
{
    __shared__ float  s_cmp[WPB][KM][9];  // 2.25 KB
    __shared__ int    s_scan[256];        // 1 KB
    __shared__ double s_red[256][4];      // 8 KB
    __shared__ int    s_last;

    const int tid = threadIdx.x, lane = tid & 31, wid = tid >> 5;
    const int bid = blockIdx.x;

    // ---- P0: count (32 points per block) + fb via ballot-rank (block 1) ----
    if (tid < 32) {
        const int p = bid * 32 + tid;                      // GRD*32 == NLL exactly
        const int4 v = reinterpret_cast<const int4*>(lidx)[p];
        const int cell = v.x * NCELL + (((v.y >> 4) * CDY + (v.z >> 4)) * CDZ + (v.w >> 4));
        atomicAdd(&g_ccnt[cell], 1);
    }
    if (bid == 1 && wid < NB) {                            // warp w -> batch w fillers
        const int b = wid;
        int c = 0;
        for (int j0 = 0; j0 < NLL && c < TK; j0 += 32) {
            const int j = j0 + lane;
            const bool pred = lidx[j * 4] != b;
            const unsigned m = __ballot_sync(FULLM, pred);
            if (pred) {
                const int rank = c + __popc(m & ((1u << lane) - 1u));
                if (rank < TK) g_fb[b * TK + rank] = j;
            }
            c += __popc(m);
        }
    }
    gsync();

    // ---- P1: block 0 exclusive scan over 1452 cells (+ self-zero counts) ----
    if (bid == 0) {
        const int base = tid * 6;
        int c[6], s = 0;
        #pragma unroll
        for (int q = 0; q < 6; ++q) {
            const int idx = base + q;
            c[q] = (idx < NCB) ? g_ccnt[idx] : 0;
            s += c[q];
        }
        s_scan[tid] = s;
        __syncthreads();
        for (int d = 1; d < 256; d <<= 1) {
            const int vv = (tid >= d) ? s_scan[tid - d] : 0;
            __syncthreads();
            s_scan[tid] += vv;
            __syncthreads();
        }
        int e = s_scan[tid] - s;
        #pragma unroll
        for (int q = 0; q < 6; ++q) {
            const int idx = base + q;
            if (idx < NCB) { g_cstart[idx] = e; g_ccur[idx] = e; g_ccnt[idx] = 0; }
            e += c[q];
        }
        if (tid == 255) g_cstart[NCB] = s_scan[255];
    }
    gsync();

    // ---- P2: scatter ----
    if (tid < 32) {
        const int p = bid * 32 + tid;
        const int4 v = reinterpret_cast<const int4*>(lidx)[p];
        const int cell = v.x * NCELL + (((v.y >> 4) * CDY + (v.z >> 4)) * CDZ + (v.w >> 4));
        const int pos = atomicAdd(&g_ccur[cell], 1);
        g_cent[pos] = (((long long)((v.y << 16) | (v.z << 8) | v.w)) << 16) | (long long)p;
    }
    gsync();

    // ---- P3: per-radar search (per-lane register top-10) + MDN ----
    {
        const int i = bid * WPB + wid;
        const int4 r = reinterpret_cast<const int4*>(ridx)[i];
        const int b = r.x, r1 = r.y, r2 = r.z, r3 = r.w;
        const int cx = r1 >> 4, cy = r2 >> 4, cz = r3 >> 4;
        const int cbase = b * NCELL;
        const int bbeg = g_cstart[cbase];
        const int bend = g_cstart[cbase + NCELL];
        const int nbL  = bend - bbeg;

        unsigned lst[TK];
        #pragma unroll 1
        for (int R = 1;; ++R) {
            const int x0 = max(cx - R, 0), x1 = min(cx + R, CDX - 1);
            const int y0 = max(cy - R, 0), y1 = min(cy + R, CDY - 1);
            const int z0 = max(cz - R, 0), z1 = min(cz + R, CDZ - 1);
            int g = INT_MAX;
            if (x0 > 0)       g = min(g, r1 - x0 * 16);
            if (x1 < CDX - 1) g = min(g, (x1 + 1) * 16 - r1);
            if (y0 > 0)       g = min(g, r2 - y0 * 16);
            if (y1 < CDY - 1) g = min(g, (y1 + 1) * 16 - r2);
            if (z0 > 0)       g = min(g, r3 - z0 * 16);
            if (z1 < CDZ - 1) g = min(g, (z1 + 1) * 16 - r3);
            const bool whole = (g == INT_MAX);
            const unsigned g2 = whole ? 0x7FFFFFFFu : (unsigned)(g * g);

            #pragma unroll
            for (int s = 0; s < TK; ++s) lst[s] = KNONE;
            int cntL = 0;

            #pragma unroll 1
            for (int xx = x0; xx <= x1; ++xx) {
                #pragma unroll 1
                for (int yy = y0; yy <= y1; ++yy) {
                    const int crow = cbase + (xx * CDY + yy) * CDZ;
                    const int beg = g_cstart[crow + z0];
                    const int end = g_cstart[crow + z1 + 1];
                    for (int j = beg + lane; j < end; j += 32) {
                        const long long e = g_cent[j];
                        const int p  = (int)(e >> 16);
                        const int d3 = (p & 255) - r3;
                        const int d2 = ((p >> 8) & 255) - r2;
                        const int d1 = ((p >> 16) & 255) - r1;
                        const unsigned dd = (unsigned)(d1 * d1 + d2 * d2 + d3 * d3);
                        if (dd < g2) {
                            ++cntL;
                            unsigned key = (dd << 16) | ((unsigned)e & 0xFFFFu);
                            #pragma unroll
                            for (int s = 0; s < TK; ++s) {   // sorted bubble-insert
                                const unsigned lo = min(key, lst[s]);
                                key = max(key, lst[s]);
                                lst[s] = lo;
                            }
                        }
                    }
                }
            }
            const unsigned cnt = __reduce_add_sync(FULLM, (unsigned)cntL);
            if (cnt >= TK || whole) break;
        }

        // merge: 10 rounds of warp-min over sorted lane heads (keys unique)
        unsigned mykey = KNONE;
        #pragma unroll
        for (int t = 0; t < TK; ++t) {
            const unsigned m = __reduce_min_sync(FULLM, lst[0]);
            if (lane == t) mykey = m;
            if (lst[0] == m) {
                #pragma unroll
                for (int s = 0; s < TK - 1; ++s) lst[s] = lst[s + 1];
                lst[TK - 1] = KNONE;
            }
        }

        // per-component precompute (lanes 0..7, width-8 trees)
        const int k = lane;
        float v = (k < KM) ? mix_logit[i * KM + k] : -INFINITY;
        float mx = v;
        #pragma unroll
        for (int d = 4; d; d >>= 1) mx = fmaxf(mx, __shfl_xor_sync(FULLM, mx, d));
        const float ex = (k < KM) ? expf(v - mx) : 0.0f;
        float sm = ex;
        #pragma unroll
        for (int d = 4; d; d >>= 1) sm += __shfl_xor_sync(FULLM, sm, d);
        const float lz = mx + logf(sm);

        float o = (k < KM) ? occ_logit[i * KM + k] : -INFINITY;
        #pragma unroll
        for (int d = 4; d; d >>= 1) o = fmaxf(o, __shfl_xor_sync(FULLM, o, d));

        if (k < KM) {
            const int bk = (i * KM + k) * 3;
            const float l0 = log_sig_off[bk], l1 = log_sig_off[bk + 1], l2 = log_sig_off[bk + 2];
            s_cmp[wid][k][0] = v - lz;
            s_cmp[wid][k][1] = mu_off[bk];
            s_cmp[wid][k][2] = mu_off[bk + 1];
            s_cmp[wid][k][3] = mu_off[bk + 2];
            s_cmp[wid][k][4] = 1.0f / (expf(2.0f * l0) + 1e-12f);
            s_cmp[wid][k][5] = 1.0f / (expf(2.0f * l1) + 1e-12f);
            s_cmp[wid][k][6] = 1.0f / (expf(2.0f * l2) + 1e-12f);
            s_cmp[wid][k][7] = 2.0f * (l0 + l1 + l2) + 3.0f * F_LOG2PI;
            s_cmp[wid][k][8] = mu_int[i * KM + k];
        }
        __syncwarp();

        // per-slot MDN + intensity (lanes 0..9)
        const bool matched = nbL > 0;
        const unsigned rm = __ballot_sync(FULLM, mykey != KNONE && lane < TK);
        const int nvalid = __popc(rm);
        float SL = 0.0f, SI = 0.0f;
        if (lane < TK) {
            const int j = (mykey != KNONE) ? (int)(mykey & 0xFFFFu)
                                           : g_fb[b * TK + (lane - nvalid)];
            const int4 lv = reinterpret_cast<const int4*>(lidx)[j];
            const float y0 = matched ? (float)(lv.w - r3) : 0.0f;
            const float y1 = matched ? (float)(lv.z - r2) : 0.0f;
            const float y2 = matched ? (float)(lv.y - r1) : 0.0f;
            const float* f = lfeat + j * CF;
            const float gi = matched ? 0.25f * (f[3] + f[7] + f[11] + f[15]) : 0.0f;

            float lp[KM]; float pm = -INFINITY;
            #pragma unroll
            for (int kk = 0; kk < KM; ++kk) {
                const float d0 = y0 - s_cmp[wid][kk][1];
                const float d1 = y1 - s_cmp[wid][kk][2];
                const float d2 = y2 - s_cmp[wid][kk][3];
                const float qv = d0 * d0 * s_cmp[wid][kk][4] + d1 * d1 * s_cmp[wid][kk][5]
                               + d2 * d2 * s_cmp[wid][kk][6];
                lp[kk] = -0.5f * (qv + s_cmp[wid][kk][7]) + s_cmp[wid][kk][0];
                pm = fmaxf(pm, lp[kk]);
            }
            float se = 0.0f;
            #pragma unroll
            for (int kk = 0; kk < KM; ++kk) se += expf(lp[kk] - pm);
            const float logp = pm + logf(se);
            SL = logp;
            float ai = 0.0f;
            #pragma unroll
            for (int kk = 0; kk < KM; ++kk)
                ai += expf(lp[kk] - logp) * fabsf(s_cmp[wid][kk][8] - gi);
            SI = ai;
        }
        #pragma unroll
        for (int d = 16; d; d >>= 1) {
            SL += __shfl_xor_sync(FULLM, SL, d);
            SI += __shfl_xor_sync(FULLM, SI, d);
        }
        if (lane == 0) {
            const float tgt = matched ? 1.0f : 0.0f;
            const float occ = tgt * softplusf(-o) + (1.0f - tgt) * softplusf(o);
            g_part[i] = make_float4(occ, tgt, tgt * SL, tgt * SI);
        }
    }

    // ---- P4: last-finishing-block deterministic reduction (ticket) ----
    __threadfence();
    __syncthreads();
    if (tid == 0) s_last = (atomicAdd(&g_done, 1) == GRD - 1);
    __syncthreads();
    if (s_last) {
        __threadfence();
        double a0 = 0, a1 = 0, a2 = 0, a3 = 0;
        for (int q = tid; q < NRR; q += 256) {
            const float4 p = g_part[q];
            a0 += p.x; a1 += p.y; a2 += p.z; a3 += p.w;
        }
        s_red[tid][0] = a0; s_red[tid][1] = a1; s_red[tid][2] = a2; s_red[tid][3] = a3;
        __syncthreads();
        for (int s = 128; s; s >>= 1) {
            if (tid < s) {
                s_red[tid][0] += s_red[tid + s][0];
                s_red[tid][1] += s_red[tid + s][1];
                s_red[tid][2] += s_red[tid + s][2];
                s_red[tid][3] += s_red[tid + s][3];
            }
            __syncthreads();
        }
        if (tid == 0) {
            const double occ_loss = s_red[0][0] / (double)NRR;
            const double cntm     = s_red[0][1];
            const double mdn_nll  = -s_red[0][2] / (cntm * (double)TK);
            const double int_loss =  s_red[0][3] / (cntm * (double)TK * (double)KM);
            out[0] = (float)(0.2 * occ_loss + 1.0 * mdn_nll + 0.1 * int_loss);
            g_done = 0;   // reset for next replay
        }
    }
}

// ---------------- launch ----------------
extern "C" void kernel_launch(void* const* d_in, const int* in_sizes, int n_in,
                              void* d_out, int out_size) {
    const float* mu_off      = (const float*)d_in[0];
    const float* log_sig_off = (const float*)d_in[1];
    const float* mu_int      = (const float*)d_in[2];
    const float* occ_logit   = (const float*)d_in[3];
    const float* mix_logit   = (const float*)d_in[4];
    const float* lfeat       = (const float*)d_in[5];
    const int*   ridx        = (const int*)d_in[6];
    const int*   lidx        = (const int*)d_in[7];
    (void)in_sizes; (void)n_in; (void)out_size;

    k_go<<<GRD, 256>>>(mu_off, log_sig_off, mu_int, occ_logit, mix_logit,
                       lfeat, ridx, lidx, (float*)d_out);
}